// round 3
// baseline (speedup 1.0000x reference)
#include <cuda_runtime.h>

// B=16, N=32, C=8, O=16. Output (fp32) concat: out0@0(256), out1@256(8192),
// out2@8448(262144), out3@270592(8388608). Total 8659200.
constexpr int OFF1 = 256;
constexpr int OFF2 = 256 + 8192;
constexpr int OFF3 = 256 + 8192 + 262144;

#define DINL __device__ __forceinline__

// Scratch (device globals, allocation-free).
__device__ __align__(16) float g_r1[16 * 16];            // [b][max8|min8]
__device__ __align__(16) float g_r2[16 * 32 * 16];       // [b,i][max8|min8]
__device__ __align__(16) float g_r3[16 * 32 * 32 * 16];  // [b,i,j][max8|min8]
// Combined x2-permutation tables for out3 (b3 folded into V):
// V[b,u,v,o] = x2[b,u,v]*W3[0:8] + x2[b,v,u]*W3[32:40] + b3   (used at (i,j))
// W[b,u,v,o] = x2[b,u,v]*W3[16:24] + x2[b,v,u]*W3[48:56]      (used at (i,k))
// U[b,u,v,o] = x2[b,u,v]*W3[64:72] + x2[b,v,u]*W3[80:88]      (used at (j,k))
__device__ __align__(16) float g_V[16 * 32 * 32 * 16];
__device__ __align__(16) float g_W[16 * 32 * 32 * 16];
__device__ __align__(16) float g_U[16 * 32 * 32 * 16];

DINL unsigned long long pk2(float lo, float hi) {
    unsigned long long r;
    asm("mov.b64 %0, {%1,%2};" : "=l"(r) : "f"(lo), "f"(hi));
    return r;
}
DINL void upk2(unsigned long long v, float& lo, float& hi) {
    asm("mov.b64 {%0,%1}, %2;" : "=f"(lo), "=f"(hi) : "l"(v));
}
DINL void fma2(unsigned long long& d, unsigned long long a, unsigned long long b) {
    asm("fma.rn.f32x2 %0, %1, %2, %0;" : "+l"(d) : "l"(a), "l"(b));
}
DINL float sigmoidf(float x) { return 1.f / (1.f + __expf(-x)); }

// ----------------------------------------------------------------------------
// Kernel 1: reductions r1/r2/r3 + x2 tables V/W/U.
// blocks 0..511: r3 per (b,i); 512..575: r2; 576: r1; 577..592: tables per b.
// ----------------------------------------------------------------------------
extern "C" __global__ void __launch_bounds__(256) k_pre(
    const float* __restrict__ x1, const float* __restrict__ x2,
    const float* __restrict__ x3, const float* __restrict__ W3,
    const float* __restrict__ b3)
{
    __shared__ float sW[96 * 16];
    __shared__ float sb[16];
    const int bx = blockIdx.x, tid = threadIdx.x;
    const int warp = tid >> 5, lane = tid & 31;
    const int c = lane & 7, g = lane >> 3;

    if (bx < 512) {  // r3[b,i,j,:] = reduce_k (exclude k==j) of x3[b,i,j,k,:]
        const float* src = x3 + bx * 8192;
        for (int jj = 0; jj < 4; jj++) {
            const int j = warp + jj * 8;
            const float* row = src + j * 256 + g * 64 + c;
            float mx = -1e30f, mn = 1e30f;
            #pragma unroll
            for (int kk = 0; kk < 8; kk++) {
                const int k = g * 8 + kk;
                const float x = row[kk * 8];
                mx = fmaxf(mx, (k == j) ? 0.f : x);
                mn = fminf(mn, (k == j) ? 1.f : x);
            }
            mx = fmaxf(mx, __shfl_xor_sync(~0u, mx, 8));
            mx = fmaxf(mx, __shfl_xor_sync(~0u, mx, 16));
            mn = fminf(mn, __shfl_xor_sync(~0u, mn, 8));
            mn = fminf(mn, __shfl_xor_sync(~0u, mn, 16));
            if (lane < 8) {
                const int r = bx * 32 + j;
                g_r3[r * 16 + c] = mx;
                g_r3[r * 16 + 8 + c] = mn;
            }
        }
    } else if (bx < 576) {  // r2[b,i,:] = reduce_j (exclude j==i) of x2[b,i,j,:]
        const int row = (bx - 512) * 8 + warp;
        const int i = row & 31;
        const float* p = x2 + row * 256 + g * 64 + c;
        float mx = -1e30f, mn = 1e30f;
        #pragma unroll
        for (int kk = 0; kk < 8; kk++) {
            const int j = g * 8 + kk;
            const float x = p[kk * 8];
            mx = fmaxf(mx, (j == i) ? 0.f : x);
            mn = fminf(mn, (j == i) ? 1.f : x);
        }
        mx = fmaxf(mx, __shfl_xor_sync(~0u, mx, 8));
        mx = fmaxf(mx, __shfl_xor_sync(~0u, mx, 16));
        mn = fminf(mn, __shfl_xor_sync(~0u, mn, 8));
        mn = fminf(mn, __shfl_xor_sync(~0u, mn, 16));
        if (lane < 8) {
            g_r2[row * 16 + c] = mx;
            g_r2[row * 16 + 8 + c] = mn;
        }
    } else if (bx == 576) {  // r1[b,:] = reduce_n of x1[b,n,:] (no exclusion)
        for (int bb = warp; bb < 16; bb += 8) {
            const float* p = x1 + bb * 256 + g * 64 + c;
            float mx = -1e30f, mn = 1e30f;
            #pragma unroll
            for (int kk = 0; kk < 8; kk++) {
                const float x = p[kk * 8];
                mx = fmaxf(mx, x);
                mn = fminf(mn, x);
            }
            mx = fmaxf(mx, __shfl_xor_sync(~0u, mx, 8));
            mx = fmaxf(mx, __shfl_xor_sync(~0u, mx, 16));
            mn = fminf(mn, __shfl_xor_sync(~0u, mn, 8));
            mn = fminf(mn, __shfl_xor_sync(~0u, mn, 16));
            if (lane < 8) {
                g_r1[bb * 16 + c] = mx;
                g_r1[bb * 16 + 8 + c] = mn;
            }
        }
    } else {  // tables for b = bx - 577
        const int b = bx - 577;
        for (int idx = tid; idx < 1536; idx += 256) sW[idx] = W3[idx];
        if (tid < 16) sb[tid] = b3[tid];
        __syncthreads();
        for (int p0 = tid; p0 < 1024; p0 += 256) {
            const int u = p0 >> 5, v = p0 & 31;
            const float* pa = x2 + (b * 1024 + p0) * 8;          // x2[b,u,v,:]
            const float* pb = x2 + (b * 1024 + v * 32 + u) * 8;  // x2[b,v,u,:]
            float xa[8], xb[8];
            #pragma unroll
            for (int cc = 0; cc < 8; cc++) { xa[cc] = pa[cc]; xb[cc] = pb[cc]; }
            const int ob = (b * 1024 + p0) * 16;
            #pragma unroll
            for (int o = 0; o < 16; o++) {
                float sv = sb[o], sw = 0.f, su = 0.f;
                #pragma unroll
                for (int cc = 0; cc < 8; cc++) {
                    sv += xa[cc] * sW[cc * 16 + o]        + xb[cc] * sW[(32 + cc) * 16 + o];
                    sw += xa[cc] * sW[(16 + cc) * 16 + o] + xb[cc] * sW[(48 + cc) * 16 + o];
                    su += xa[cc] * sW[(64 + cc) * 16 + o] + xb[cc] * sW[(80 + cc) * 16 + o];
                }
                g_V[ob + o] = sv;
                g_W[ob + o] = sw;
                g_U[ob + o] = su;
            }
        }
    }
}

// ----------------------------------------------------------------------------
// Kernel 2: out0/out1/out2. Warp per row; lanes = (o 0..15) x (half 0..1).
// blocks 0..2047: out2; 2048..2111: out1; 2112: out0.
// ----------------------------------------------------------------------------
extern "C" __global__ void __launch_bounds__(256) k_out_small(
    const float* __restrict__ x0, const float* __restrict__ x1,
    const float* __restrict__ x2,
    const float* __restrict__ W0, const float* __restrict__ b0,
    const float* __restrict__ W1, const float* __restrict__ b1,
    const float* __restrict__ W2, const float* __restrict__ b2,
    float* __restrict__ out)
{
    __shared__ float sW2[64 * 16];
    __shared__ float sb2[16];
    const int bx = blockIdx.x, tid = threadIdx.x;
    const int warp = tid >> 5, lane = tid & 31;
    const int o = lane & 15, hf = lane >> 4;

    for (int idx = tid; idx < 1024; idx += 256) sW2[idx] = W2[idx];
    if (tid < 16) sb2[tid] = b2[tid];
    __syncthreads();

    if (bx < 2048) {  // out2: f2 = [x1[b,u], x2[b,u,v], r3[b,u,v]] per half
        const int row = bx * 8 + warp;  // (b,i,j)
        const int b = row >> 10, i = (row >> 5) & 31, j = row & 31;
        const int u = hf ? j : i, v = hf ? i : j;
        const int wb = hf * 32;
        const float* px1 = x1 + (b * 32 + u) * 8;
        const float* px2 = x2 + ((b * 32 + u) * 32 + v) * 8;
        const float* pr3 = g_r3 + ((b * 32 + u) * 32 + v) * 16;
        float acc = 0.f;
        #pragma unroll
        for (int cc = 0; cc < 8; cc++)  acc += px1[cc] * sW2[(wb + cc) * 16 + o];
        #pragma unroll
        for (int cc = 0; cc < 8; cc++)  acc += px2[cc] * sW2[(wb + 8 + cc) * 16 + o];
        #pragma unroll
        for (int cc = 0; cc < 16; cc++) acc += pr3[cc] * sW2[(wb + 16 + cc) * 16 + o];
        acc += __shfl_xor_sync(~0u, acc, 16);
        if (hf == 0) out[OFF2 + row * 16 + o] = sigmoidf(acc + sb2[o]);
    } else if (bx < 2112) {  // out1: f1 = [x0[b], x1[b,i], r2[b,i]]
        const int row = (bx - 2048) * 8 + warp;  // (b,i)
        const int b = row >> 5;
        float acc = 0.f;
        if (hf == 0) {
            const float* px0 = x0 + b * 8;
            const float* px1 = x1 + row * 8;
            #pragma unroll
            for (int cc = 0; cc < 8; cc++) acc += px0[cc] * __ldg(W1 + cc * 16 + o);
            #pragma unroll
            for (int cc = 0; cc < 8; cc++) acc += px1[cc] * __ldg(W1 + (8 + cc) * 16 + o);
        } else {
            const float* pr2 = g_r2 + row * 16;
            #pragma unroll
            for (int cc = 0; cc < 16; cc++) acc += pr2[cc] * __ldg(W1 + (16 + cc) * 16 + o);
        }
        acc += __shfl_xor_sync(~0u, acc, 16);
        if (hf == 0) out[OFF1 + row * 16 + o] = sigmoidf(acc + __ldg(b1 + o));
    } else {  // out0: f0 = [x0[b], r1[b]]
        for (int bb = warp; bb < 16; bb += 8) {
            float acc = 0.f;
            if (hf == 0) {
                #pragma unroll
                for (int c2 = 0; c2 < 12; c2++) {
                    const float f = (c2 < 8) ? x0[bb * 8 + c2] : g_r1[bb * 16 + c2 - 8];
                    acc += f * __ldg(W0 + c2 * 16 + o);
                }
            } else {
                #pragma unroll
                for (int c2 = 12; c2 < 24; c2++)
                    acc += g_r1[bb * 16 + c2 - 8] * __ldg(W0 + c2 * 16 + o);
            }
            acc += __shfl_xor_sync(~0u, acc, 16);
            if (hf == 0) out[bb * 16 + o] = sigmoidf(acc + __ldg(b0 + o));
        }
    }
}

// ----------------------------------------------------------------------------
// Kernel 3: out3. Block per (b,i). Smem: sA[u][v]=x3[b,i,u,v], sB[u][v]=
// x3[b,u,i,v], sC[u][v]=x3[b,u,v,i] (pitch 264 floats), plus V[b,i,:,:].
// Thread = (k = tid>>3, og = tid&7) -> outputs {2og,2og+1} for all j.
// ----------------------------------------------------------------------------
extern "C" __global__ void __launch_bounds__(256, 1) k_out3(
    const float* __restrict__ x3, const float* __restrict__ W3,
    float* __restrict__ out)
{
    extern __shared__ float sm[];
    float* sA = sm;
    float* sB = sm + 8448;
    float* sC = sm + 16896;
    float* sV = sm + 25344;  // 512 floats

    const int bx = blockIdx.x, tid = threadIdx.x;
    const int b = bx >> 5, i = bx & 31;

    {
        const int base_bi = bx * 8192;
        const int base_b = b * 262144;
        for (int idx = tid; idx < 8192; idx += 256) {
            const int u = idx >> 8;
            const int r = idx & 255;           // v*8 + c
            const int v = r >> 3, c = r & 7;
            const int dst = u * 264 + r;
            sA[dst] = x3[base_bi + idx];
            sB[dst] = x3[base_b + u * 8192 + i * 256 + r];
            sC[dst] = x3[base_b + u * 8192 + v * 256 + i * 8 + c];
        }
        for (int idx = tid; idx < 512; idx += 256) sV[idx] = g_V[bx * 512 + idx];
    }

    const int og = tid & 7;
    const int k = tid >> 3;

    // Weight channel-pairs in regs: wA for output 2og, wB for 2og+1.
    // wX[t*4+p] = {W3[16t+8+2p, o], W3[16t+8+2p+1, o]}
    unsigned long long wA[24], wB[24];
    #pragma unroll
    for (int t = 0; t < 6; t++) {
        #pragma unroll
        for (int p = 0; p < 4; p++) {
            const int r0 = (16 * t + 8 + 2 * p) * 16;
            const int r1 = r0 + 16;
            wA[t * 4 + p] = pk2(__ldg(W3 + r0 + 2 * og),     __ldg(W3 + r1 + 2 * og));
            wB[t * 4 + p] = pk2(__ldg(W3 + r0 + 2 * og + 1), __ldg(W3 + r1 + 2 * og + 1));
        }
    }
    const float2 wt2 = *(const float2*)(g_W + (bx * 32 + k) * 16 + 2 * og);
    __syncthreads();

    const int outbase = OFF3 + bx * 16384 + k * 16 + 2 * og;  // + j*512
    const int ubase = (b * 1024 + k) * 16 + 2 * og;           // + j*512

#define PROC(S, OFFS, T)                                                        \
    {                                                                           \
        const ulonglong2* q = (const ulonglong2*)((S) + (OFFS));                \
        const ulonglong2 q0 = q[0], q1 = q[1];                                  \
        fma2(accA, q0.x, wA[(T) * 4 + 0]); fma2(accB, q0.x, wB[(T) * 4 + 0]);   \
        fma2(accA, q0.y, wA[(T) * 4 + 1]); fma2(accB, q0.y, wB[(T) * 4 + 1]);   \
        fma2(accA, q1.x, wA[(T) * 4 + 2]); fma2(accB, q1.x, wB[(T) * 4 + 2]);   \
        fma2(accA, q1.y, wA[(T) * 4 + 3]); fma2(accB, q1.y, wB[(T) * 4 + 3]);   \
    }

    const int ko = k * 264, k8 = k * 8;
    for (int j = 0; j < 32; j++) {
        unsigned long long accA = 0ull, accB = 0ull;
        const int jo = j * 264, j8 = j * 8;
        PROC(sA, jo + k8, 0);   // x3[b,i,j,k] * W3[8:16]
        PROC(sA, ko + j8, 1);   // x3[b,i,k,j] * W3[24:32]
        PROC(sB, jo + k8, 2);   // x3[b,j,i,k] * W3[40:48]
        PROC(sB, ko + j8, 3);   // x3[b,k,i,j] * W3[56:64]
        PROC(sC, jo + k8, 4);   // x3[b,j,k,i] * W3[72:80]
        PROC(sC, ko + j8, 5);   // x3[b,k,j,i] * W3[88:96]
        float a0, a1, c0, c1;
        upk2(accA, a0, a1);
        upk2(accB, c0, c1);
        const float2 V2 = *(const float2*)(sV + j * 16 + 2 * og);
        const float2 U2 = *(const float2*)(g_U + ubase + j * 512);
        const float sx = a0 + a1 + V2.x + wt2.x + U2.x;
        const float sy = c0 + c1 + V2.y + wt2.y + U2.y;
        float2 rr;
        rr.x = sigmoidf(sx);
        rr.y = sigmoidf(sy);
        *(float2*)(out + outbase + j * 512) = rr;
    }
#undef PROC
}

// ----------------------------------------------------------------------------
extern "C" void kernel_launch(void* const* d_in, const int* in_sizes, int n_in,
                              void* d_out, int out_size) {
    const float *x0 = nullptr, *x1 = nullptr, *x2 = nullptr, *x3 = nullptr;
    const float *W0 = nullptr, *W1 = nullptr, *W2 = nullptr, *W3 = nullptr;
    const float* bs[4] = {nullptr, nullptr, nullptr, nullptr};
    int nb = 0;
    for (int ii = 0; ii < n_in; ii++) {
        const float* p = (const float*)d_in[ii];
        switch (in_sizes[ii]) {
            case 128:     x0 = p; break;
            case 4096:    x1 = p; break;
            case 131072:  x2 = p; break;
            case 4194304: x3 = p; break;
            case 384:     W0 = p; break;
            case 512:     W1 = p; break;
            case 1024:    W2 = p; break;
            case 1536:    W3 = p; break;
            case 16:      if (nb < 4) bs[nb++] = p; break;
        }
    }
    const float *b0 = bs[0], *b1 = bs[1], *b2 = bs[2], *b3 = bs[3];
    float* out = (float*)d_out;

    cudaFuncSetAttribute(k_out3, cudaFuncAttributeMaxDynamicSharedMemorySize, 103424);

    k_pre<<<593, 256>>>(x1, x2, x3, W3, b3);
    k_out_small<<<2113, 256>>>(x0, x1, x2, W0, b0, W1, b1, W2, b2, out);
    k_out3<<<512, 256, 103424>>>(x3, W3, out);
}

// round 4
// speedup vs baseline: 1.8177x; 1.8177x over previous
#include <cuda_runtime.h>

// B=16, N=32, C=8, O=16. Output (fp32) concat: out0@0(256), out1@256(8192),
// out2@8448(262144), out3@270592(8388608). Total 8659200.
constexpr int OFF1 = 256;
constexpr int OFF2 = 256 + 8192;
constexpr int OFF3 = 256 + 8192 + 262144;

#define DINL __device__ __forceinline__

// Scratch (device globals, allocation-free).
__device__ __align__(16) float g_r1[16 * 16];            // [b][max8|min8]
__device__ __align__(16) float g_r2[16 * 32 * 16];       // [b,i][max8|min8]
__device__ __align__(16) float g_r3[16 * 32 * 32 * 16];  // [b,i,j][max8|min8]
// Combined x2-permutation tables for out3 (b3 folded into V):
// V[b,u,v,o] = x2[b,u,v]*W3[0:8]  + x2[b,v,u]*W3[32:40] + b3  (used at (i,j))
// W[b,u,v,o] = x2[b,u,v]*W3[16:24] + x2[b,v,u]*W3[48:56]      (used at (i,k))
// U[b,u,v,o] = x2[b,u,v]*W3[64:72] + x2[b,v,u]*W3[80:88]      (used at (j,k))
__device__ __align__(16) float g_V[16 * 32 * 32 * 16];
__device__ __align__(16) float g_W[16 * 32 * 32 * 16];
__device__ __align__(16) float g_U[16 * 32 * 32 * 16];

DINL unsigned long long pk2(float lo, float hi) {
    unsigned long long r;
    asm("mov.b64 %0, {%1,%2};" : "=l"(r) : "f"(lo), "f"(hi));
    return r;
}
DINL void upk2(unsigned long long v, float& lo, float& hi) {
    asm("mov.b64 {%0,%1}, %2;" : "=f"(lo), "=f"(hi) : "l"(v));
}
DINL void fma2(unsigned long long& d, unsigned long long a, unsigned long long b) {
    asm("fma.rn.f32x2 %0, %1, %2, %0;" : "+l"(d) : "l"(a), "l"(b));
}
DINL float sigmoidf(float x) { return 1.f / (1.f + __expf(-x)); }

// ----------------------------------------------------------------------------
// Kernel 1a: reductions r3/r2/r1. Thread per (row, channel-pair).
// blocks 0..255: r3 (16384 rows x 4 cp). 256..263: r2. 264: r1.
// Fully unrolled 32 x LDG.64 per thread -> MLP~32, tiny reg count.
// ----------------------------------------------------------------------------
extern "C" __global__ void __launch_bounds__(256) k_reduce(
    const float* __restrict__ x1, const float* __restrict__ x2,
    const float* __restrict__ x3)
{
    const int bx = blockIdx.x, tid = threadIdx.x;

    if (bx < 256) {
        const int gid = bx * 256 + tid;
        const int row = gid >> 2, cp = gid & 3;   // row = b*1024 + i*32 + j
        const int j = row & 31;
        const float2* p = (const float2*)(x3 + row * 256) + cp;
        float mx0 = -1e30f, mx1 = -1e30f, mn0 = 1e30f, mn1 = 1e30f;
        #pragma unroll
        for (int k = 0; k < 32; k++) {
            const float2 v = p[k * 4];
            const bool ex = (k == j);
            mx0 = fmaxf(mx0, ex ? 0.f : v.x);
            mx1 = fmaxf(mx1, ex ? 0.f : v.y);
            mn0 = fminf(mn0, ex ? 1.f : v.x);
            mn1 = fminf(mn1, ex ? 1.f : v.y);
        }
        float* d = g_r3 + row * 16 + cp * 2;
        d[0] = mx0; d[1] = mx1; d[8] = mn0; d[9] = mn1;
    } else if (bx < 264) {
        const int gid = (bx - 256) * 256 + tid;
        const int row = gid >> 2, cp = gid & 3;   // row = b*32 + i
        const int i = row & 31;
        const float2* p = (const float2*)(x2 + row * 256) + cp;
        float mx0 = -1e30f, mx1 = -1e30f, mn0 = 1e30f, mn1 = 1e30f;
        #pragma unroll
        for (int jn = 0; jn < 32; jn++) {
            const float2 v = p[jn * 4];
            const bool ex = (jn == i);
            mx0 = fmaxf(mx0, ex ? 0.f : v.x);
            mx1 = fmaxf(mx1, ex ? 0.f : v.y);
            mn0 = fminf(mn0, ex ? 1.f : v.x);
            mn1 = fminf(mn1, ex ? 1.f : v.y);
        }
        float* d = g_r2 + row * 16 + cp * 2;
        d[0] = mx0; d[1] = mx1; d[8] = mn0; d[9] = mn1;
    } else {
        if (tid < 64) {
            const int row = tid >> 2, cp = tid & 3;   // row = b
            const float2* p = (const float2*)(x1 + row * 256) + cp;
            float mx0 = -1e30f, mx1 = -1e30f, mn0 = 1e30f, mn1 = 1e30f;
            #pragma unroll
            for (int nn = 0; nn < 32; nn++) {
                const float2 v = p[nn * 4];
                mx0 = fmaxf(mx0, v.x);
                mx1 = fmaxf(mx1, v.y);
                mn0 = fminf(mn0, v.x);
                mn1 = fminf(mn1, v.y);
            }
            float* d = g_r1 + row * 16 + cp * 2;
            d[0] = mx0; d[1] = mx1; d[8] = mn0; d[9] = mn1;
        }
    }
}

// ----------------------------------------------------------------------------
// Kernel 1b: x2 tables V/W/U. Thread per (b,u,v,o): 262144 threads.
// ----------------------------------------------------------------------------
extern "C" __global__ void __launch_bounds__(256) k_tables(
    const float* __restrict__ x2, const float* __restrict__ W3,
    const float* __restrict__ b3)
{
    __shared__ float sW[96 * 16];
    __shared__ float sb[16];
    const int bx = blockIdx.x, tid = threadIdx.x;
    for (int idx = tid; idx < 1536; idx += 256) sW[idx] = W3[idx];
    if (tid < 16) sb[tid] = b3[tid];
    __syncthreads();

    const int gid = bx * 256 + tid;
    const int o = gid & 15;
    const int e = gid >> 4;            // b*1024 + u*32 + v
    const int b = e >> 10;
    const int u = (e >> 5) & 31, v = e & 31;

    const float4* pa = (const float4*)(x2 + e * 8);
    const float4* pb = (const float4*)(x2 + (b * 1024 + v * 32 + u) * 8);
    const float4 a0 = pa[0], a1 = pa[1];
    const float4 b0v = pb[0], b1v = pb[1];
    float xa[8] = {a0.x, a0.y, a0.z, a0.w, a1.x, a1.y, a1.z, a1.w};
    float xb[8] = {b0v.x, b0v.y, b0v.z, b0v.w, b1v.x, b1v.y, b1v.z, b1v.w};

    float sv = sb[o], sw = 0.f, su = 0.f;
    #pragma unroll
    for (int cc = 0; cc < 8; cc++) {
        sv += xa[cc] * sW[cc * 16 + o]        + xb[cc] * sW[(32 + cc) * 16 + o];
        sw += xa[cc] * sW[(16 + cc) * 16 + o] + xb[cc] * sW[(48 + cc) * 16 + o];
        su += xa[cc] * sW[(64 + cc) * 16 + o] + xb[cc] * sW[(80 + cc) * 16 + o];
    }
    g_V[gid] = sv;
    g_W[gid] = sw;
    g_U[gid] = su;
}

// ----------------------------------------------------------------------------
// Kernel 2: out0/out1/out2. Warp per row; lanes = (o 0..15) x (half 0..1).
// blocks 0..2047: out2; 2048..2111: out1; 2112: out0.
// ----------------------------------------------------------------------------
extern "C" __global__ void __launch_bounds__(256) k_out_small(
    const float* __restrict__ x0, const float* __restrict__ x1,
    const float* __restrict__ x2,
    const float* __restrict__ W0, const float* __restrict__ b0,
    const float* __restrict__ W1, const float* __restrict__ b1,
    const float* __restrict__ W2, const float* __restrict__ b2,
    float* __restrict__ out)
{
    __shared__ float sW2[64 * 16];
    __shared__ float sb2[16];
    const int bx = blockIdx.x, tid = threadIdx.x;
    const int warp = tid >> 5, lane = tid & 31;
    const int o = lane & 15, hf = lane >> 4;

    for (int idx = tid; idx < 1024; idx += 256) sW2[idx] = W2[idx];
    if (tid < 16) sb2[tid] = b2[tid];
    __syncthreads();

    if (bx < 2048) {  // out2: f2 = [x1[b,u], x2[b,u,v], r3[b,u,v]] per half
        const int row = bx * 8 + warp;  // (b,i,j)
        const int b = row >> 10, i = (row >> 5) & 31, j = row & 31;
        const int u = hf ? j : i, v = hf ? i : j;
        const int wb = hf * 32;
        const float* px1 = x1 + (b * 32 + u) * 8;
        const float* px2 = x2 + ((b * 32 + u) * 32 + v) * 8;
        const float* pr3 = g_r3 + ((b * 32 + u) * 32 + v) * 16;
        float acc = 0.f;
        #pragma unroll
        for (int cc = 0; cc < 8; cc++)  acc += px1[cc] * sW2[(wb + cc) * 16 + o];
        #pragma unroll
        for (int cc = 0; cc < 8; cc++)  acc += px2[cc] * sW2[(wb + 8 + cc) * 16 + o];
        #pragma unroll
        for (int cc = 0; cc < 16; cc++) acc += pr3[cc] * sW2[(wb + 16 + cc) * 16 + o];
        acc += __shfl_xor_sync(~0u, acc, 16);
        if (hf == 0) out[OFF2 + row * 16 + o] = sigmoidf(acc + sb2[o]);
    } else if (bx < 2112) {  // out1: f1 = [x0[b], x1[b,i], r2[b,i]]
        const int row = (bx - 2048) * 8 + warp;  // (b,i)
        const int b = row >> 5;
        float acc = 0.f;
        if (hf == 0) {
            const float* px0 = x0 + b * 8;
            const float* px1 = x1 + row * 8;
            #pragma unroll
            for (int cc = 0; cc < 8; cc++) acc += px0[cc] * __ldg(W1 + cc * 16 + o);
            #pragma unroll
            for (int cc = 0; cc < 8; cc++) acc += px1[cc] * __ldg(W1 + (8 + cc) * 16 + o);
        } else {
            const float* pr2 = g_r2 + row * 16;
            #pragma unroll
            for (int cc = 0; cc < 16; cc++) acc += pr2[cc] * __ldg(W1 + (16 + cc) * 16 + o);
        }
        acc += __shfl_xor_sync(~0u, acc, 16);
        if (hf == 0) out[OFF1 + row * 16 + o] = sigmoidf(acc + __ldg(b1 + o));
    } else {  // out0: f0 = [x0[b], r1[b]]
        for (int bb = warp; bb < 16; bb += 8) {
            float acc = 0.f;
            if (hf == 0) {
                #pragma unroll
                for (int c2 = 0; c2 < 12; c2++) {
                    const float f = (c2 < 8) ? x0[bb * 8 + c2] : g_r1[bb * 16 + c2 - 8];
                    acc += f * __ldg(W0 + c2 * 16 + o);
                }
            } else {
                #pragma unroll
                for (int c2 = 12; c2 < 24; c2++)
                    acc += g_r1[bb * 16 + c2 - 8] * __ldg(W0 + c2 * 16 + o);
            }
            acc += __shfl_xor_sync(~0u, acc, 16);
            if (hf == 0) out[bb * 16 + o] = sigmoidf(acc + __ldg(b0 + o));
        }
    }
}

// ----------------------------------------------------------------------------
// Kernel 3: out3. Block per (b,i). Smem: sA[u][v]=x3[b,i,u,v], sB[u][v]=
// x3[b,u,i,v], sC[u][v]=x3[b,u,v,i] (pitch 264 floats), plus V[b,i,:,:].
// Thread = (k = tid>>3, og = tid&7) -> outputs {2og,2og+1} for all j.
// ----------------------------------------------------------------------------
extern "C" __global__ void __launch_bounds__(256, 1) k_out3(
    const float* __restrict__ x3, const float* __restrict__ W3,
    float* __restrict__ out)
{
    extern __shared__ float sm[];
    float* sA = sm;
    float* sB = sm + 8448;
    float* sC = sm + 16896;
    float* sV = sm + 25344;  // 512 floats

    const int bx = blockIdx.x, tid = threadIdx.x;
    const int b = bx >> 5, i = bx & 31;

    {
        const int base_bi = bx * 8192;
        const int base_b = b * 262144;
        for (int idx = tid; idx < 8192; idx += 256) {
            const int u = idx >> 8;
            const int r = idx & 255;           // v*8 + c
            const int v = r >> 3, c = r & 7;
            const int dst = u * 264 + r;
            sA[dst] = x3[base_bi + idx];
            sB[dst] = x3[base_b + u * 8192 + i * 256 + r];
            sC[dst] = x3[base_b + u * 8192 + v * 256 + i * 8 + c];
        }
        for (int idx = tid; idx < 512; idx += 256) sV[idx] = g_V[bx * 512 + idx];
    }

    const int og = tid & 7;
    const int k = tid >> 3;

    // Weight channel-pairs in regs: wA for output 2og, wB for 2og+1.
    unsigned long long wA[24], wB[24];
    #pragma unroll
    for (int t = 0; t < 6; t++) {
        #pragma unroll
        for (int p = 0; p < 4; p++) {
            const int r0 = (16 * t + 8 + 2 * p) * 16;
            const int r1 = r0 + 16;
            wA[t * 4 + p] = pk2(__ldg(W3 + r0 + 2 * og),     __ldg(W3 + r1 + 2 * og));
            wB[t * 4 + p] = pk2(__ldg(W3 + r0 + 2 * og + 1), __ldg(W3 + r1 + 2 * og + 1));
        }
    }
    const float2 wt2 = *(const float2*)(g_W + (bx * 32 + k) * 16 + 2 * og);
    __syncthreads();

    const int outbase = OFF3 + bx * 16384 + k * 16 + 2 * og;  // + j*512
    const float* pU = g_U + (b * 1024 + k) * 16 + 2 * og;     // + j*512

#define PROC(S, OFFS, T)                                                        \
    {                                                                           \
        const ulonglong2* q = (const ulonglong2*)((S) + (OFFS));                \
        const ulonglong2 q0 = q[0], q1 = q[1];                                  \
        fma2(accA, q0.x, wA[(T) * 4 + 0]); fma2(accB, q0.x, wB[(T) * 4 + 0]);   \
        fma2(accA, q0.y, wA[(T) * 4 + 1]); fma2(accB, q0.y, wB[(T) * 4 + 1]);   \
        fma2(accA, q1.x, wA[(T) * 4 + 2]); fma2(accB, q1.x, wB[(T) * 4 + 2]);   \
        fma2(accA, q1.y, wA[(T) * 4 + 3]); fma2(accB, q1.y, wB[(T) * 4 + 3]);   \
    }

    const int ko = k * 264, k8 = k * 8;
    // Prefetch U for j=0 so the L2 latency overlaps the FFMA2 chain.
    float2 U2 = *(const float2*)pU;
    for (int j = 0; j < 32; j++) {
        float2 U2n;
        if (j < 31) U2n = *(const float2*)(pU + (j + 1) * 512);
        unsigned long long accA = 0ull, accB = 0ull;
        const int jo = j * 264, j8 = j * 8;
        PROC(sA, jo + k8, 0);   // x3[b,i,j,k] * W3[8:16]
        PROC(sA, ko + j8, 1);   // x3[b,i,k,j] * W3[24:32]
        PROC(sB, jo + k8, 2);   // x3[b,j,i,k] * W3[40:48]
        PROC(sB, ko + j8, 3);   // x3[b,k,i,j] * W3[56:64]
        PROC(sC, jo + k8, 4);   // x3[b,j,k,i] * W3[72:80]
        PROC(sC, ko + j8, 5);   // x3[b,k,j,i] * W3[88:96]
        float a0, a1, c0, c1;
        upk2(accA, a0, a1);
        upk2(accB, c0, c1);
        const float2 V2 = *(const float2*)(sV + j * 16 + 2 * og);
        const float sx = a0 + a1 + V2.x + wt2.x + U2.x;
        const float sy = c0 + c1 + V2.y + wt2.y + U2.y;
        float2 rr;
        rr.x = sigmoidf(sx);
        rr.y = sigmoidf(sy);
        *(float2*)(out + outbase + j * 512) = rr;
        U2 = U2n;
    }
#undef PROC
}

// ----------------------------------------------------------------------------
extern "C" void kernel_launch(void* const* d_in, const int* in_sizes, int n_in,
                              void* d_out, int out_size) {
    const float *x0 = nullptr, *x1 = nullptr, *x2 = nullptr, *x3 = nullptr;
    const float *W0 = nullptr, *W1 = nullptr, *W2 = nullptr, *W3 = nullptr;
    const float* bs[4] = {nullptr, nullptr, nullptr, nullptr};
    int nb = 0;
    for (int ii = 0; ii < n_in; ii++) {
        const float* p = (const float*)d_in[ii];
        switch (in_sizes[ii]) {
            case 128:     x0 = p; break;
            case 4096:    x1 = p; break;
            case 131072:  x2 = p; break;
            case 4194304: x3 = p; break;
            case 384:     W0 = p; break;
            case 512:     W1 = p; break;
            case 1024:    W2 = p; break;
            case 1536:    W3 = p; break;
            case 16:      if (nb < 4) bs[nb++] = p; break;
        }
    }
    const float *b0 = bs[0], *b1 = bs[1], *b2 = bs[2], *b3 = bs[3];
    float* out = (float*)d_out;

    cudaFuncSetAttribute(k_out3, cudaFuncAttributeMaxDynamicSharedMemorySize, 103424);

    k_reduce<<<265, 256>>>(x1, x2, x3);
    k_tables<<<1024, 256>>>(x2, W3, b3);
    k_out_small<<<2113, 256>>>(x0, x1, x2, W0, b0, W1, b1, W2, b2, out);
    k_out3<<<512, 256, 103424>>>(x3, W3, out);
}